// round 6
// baseline (speedup 1.0000x reference)
#include <cuda_runtime.h>
#include <stdint.h>
#include <math.h>

#define NI 700
#define NIP 704
#define H 4096
#define T 1000
#define O 20
#define KC (NIP/4)   // 176 u32 chunks per row
#define KPAD 177

#define CSZ 8                 // cluster size (CTAs) for the recurrence
#define THR 256               // threads per recurrence CTA
#define WPC (H / 4 / CSZ)     // 128 words (512 neurons) per CTA
#define REG 512               // spike-region capacity per producer CTA

// ---------------- scratch (static device memory; no allocs) ----------------
__device__ __align__(16) int8_t g_w1p[H * NIP];        // w1 packed int8, padded 700->704
__device__ __align__(16) int8_t g_sp [T * NIP];        // spikes packed int8 (0/1), padded
__device__ __align__(16) int8_t g_v1T[(size_t)H * H];  // v1T[k][h] = v1[h][k], int8
__device__ __align__(16) int8_t g_w2T[H * 32];         // w2T[k][o], padded 20->32
__device__ __align__(16) int    g_in [T * H];          // in_all[t][h], int32 (exact)
__device__ int g_mode;  // input dtype: 0=int64, 1=int32, 2=float32, 3=float64

// ---------------- input dtype probe (on w1: dense values in [-8,7]) ----------------
__global__ void detect_dtype_kernel(const void* __restrict__ p) {
    const int* w = (const int*)p;
    bool i64 = true;
    for (int i = 0; i < 8; i++) {
        int lo = w[2 * i], hi = w[2 * i + 1];
        if (!(lo >= -8 && lo <= 7 && hi == (lo < 0 ? -1 : 0))) i64 = false;
    }
    if (i64) { g_mode = 0; return; }
    bool i32 = true;
    for (int i = 0; i < 16; i++) {
        int v = w[i];
        if (!(v >= -8 && v <= 7)) i32 = false;
    }
    if (i32) { g_mode = 1; return; }
    bool f32 = true;
    for (int i = 0; i < 16; i++) {
        float f = __int_as_float(w[i]);
        if (!(isfinite(f) && fabsf(f) <= 8.0f && f == truncf(f))) f32 = false;
    }
    if (f32) { g_mode = 2; return; }
    g_mode = 3;  // float64
}

__device__ __forceinline__ int load_elem(const void* p, long idx) {
    switch (g_mode) {
        case 0:  return (int)((const long long*)p)[idx];
        case 1:  return ((const int*)p)[idx];
        case 2:  return (int)((const float*)p)[idx];
        default: return (int)((const double*)p)[idx];
    }
}

// Output read as float32 by the harness. |values| < 2^24 -> exact.
__device__ __forceinline__ void store_out(void* out, int idx, int val) {
    ((float*)out)[idx] = (float)val;
}

// DSMEM: store val into rank's shared memory at the peer address of laddr.
__device__ __forceinline__ void st_remote(uint32_t laddr, uint32_t rank, int val) {
    uint32_t ra;
    asm volatile("mapa.shared::cluster.u32 %0, %1, %2;" : "=r"(ra) : "r"(laddr), "r"(rank));
    asm volatile("st.shared::cluster.u32 [%0], %1;" :: "r"(ra), "r"(val) : "memory");
}

// ---------------- pack kernels ----------------
__global__ void pack_w1_kernel(const void* __restrict__ w1) {
    int idx = blockIdx.x * blockDim.x + threadIdx.x;
    if (idx >= H * NIP) return;
    int h = idx / NIP, c = idx - h * NIP;
    g_w1p[idx] = (c < NI) ? (int8_t)load_elem(w1, (long)h * NI + c) : (int8_t)0;
}

__global__ void pack_sp_kernel(const void* __restrict__ spk) {
    int idx = blockIdx.x * blockDim.x + threadIdx.x;
    if (idx >= T * NIP) return;
    int t = idx / NIP, c = idx - t * NIP;
    g_sp[idx] = (c < NI) ? (int8_t)load_elem(spk, (long)t * NI + c) : (int8_t)0;
}

__global__ void pack_w2_kernel(const void* __restrict__ w2) {
    int idx = blockIdx.x * blockDim.x + threadIdx.x;
    if (idx >= H * 32) return;
    int k = idx >> 5, o = idx & 31;
    g_w2T[idx] = (o < O) ? (int8_t)load_elem(w2, (long)o * H + k) : (int8_t)0;
}

// tiled transpose: v1[h][k] -> g_v1T[k][h] (int8)
__global__ void pack_v1T_kernel(const void* __restrict__ v1) {
    __shared__ int8_t tile[64][65];
    int kb = blockIdx.x * 64;
    int hb = blockIdx.y * 64;
    for (int i = threadIdx.x; i < 64 * 64; i += 256) {
        int r = i >> 6, c = i & 63;          // r = h-local, c = k-local
        tile[c][r] = (int8_t)load_elem(v1, (long)(hb + r) * H + (kb + c));
    }
    __syncthreads();
    for (int i = threadIdx.x; i < 64 * 64; i += 256) {
        int r = i >> 6, c = i & 63;          // r = k-local, c = h-local
        g_v1T[(size_t)(kb + r) * H + (hb + c)] = tile[r][c];
    }
}

// ---------------- feed-forward GEMM: in_all[t][h] = sum_i w1[h][i]*spk[t][i] ----------------
__global__ void gemm_in_kernel() {
    __shared__ int swt[32 * KPAD];
    __shared__ int sst[32 * KPAD];
    const int tid = threadIdx.x;
    const int hb = blockIdx.x * 32;
    const int tb = blockIdx.y * 32;
    const int* w32 = (const int*)g_w1p;
    const int* s32 = (const int*)g_sp;

    for (int i = tid; i < 32 * KC; i += 64) {
        int r = i / KC, c = i - r * KC;
        swt[r * KPAD + c] = w32[(hb + r) * KC + c];
    }
    for (int i = tid; i < 32 * KC; i += 64) {
        int r = i / KC, c = i - r * KC;
        int t = tb + r;
        sst[r * KPAD + c] = (t < T) ? s32[t * KC + c] : 0;
    }
    __syncthreads();

    const int h0 = (tid >> 3) * 4;   // 0..28
    const int t0 = (tid & 7) * 4;    // 0..28
    int acc[4][4];
#pragma unroll
    for (int i = 0; i < 4; i++)
#pragma unroll
        for (int j = 0; j < 4; j++) acc[i][j] = 0;

    const int* wp = &swt[h0 * KPAD];
    const int* sp = &sst[t0 * KPAD];
    for (int c = 0; c < KC; c++) {
        int w0 = wp[c], w1v = wp[KPAD + c], w2v = wp[2 * KPAD + c], w3v = wp[3 * KPAD + c];
        int s0 = sp[c], s1 = sp[KPAD + c], s2 = sp[2 * KPAD + c], s3 = sp[3 * KPAD + c];
        acc[0][0] = __dp4a(w0, s0, acc[0][0]); acc[0][1] = __dp4a(w0, s1, acc[0][1]);
        acc[0][2] = __dp4a(w0, s2, acc[0][2]); acc[0][3] = __dp4a(w0, s3, acc[0][3]);
        acc[1][0] = __dp4a(w1v, s0, acc[1][0]); acc[1][1] = __dp4a(w1v, s1, acc[1][1]);
        acc[1][2] = __dp4a(w1v, s2, acc[1][2]); acc[1][3] = __dp4a(w1v, s3, acc[1][3]);
        acc[2][0] = __dp4a(w2v, s0, acc[2][0]); acc[2][1] = __dp4a(w2v, s1, acc[2][1]);
        acc[2][2] = __dp4a(w2v, s2, acc[2][2]); acc[2][3] = __dp4a(w2v, s3, acc[2][3]);
        acc[3][0] = __dp4a(w3v, s0, acc[3][0]); acc[3][1] = __dp4a(w3v, s1, acc[3][1]);
        acc[3][2] = __dp4a(w3v, s2, acc[3][2]); acc[3][3] = __dp4a(w3v, s3, acc[3][3]);
    }
#pragma unroll
    for (int ti = 0; ti < 4; ti++) {
        int t = tb + t0 + ti;
        if (t < T) {
            int4 v = make_int4(acc[0][ti], acc[1][ti], acc[2][ti], acc[3][ti]);
            *(int4*)(g_in + (size_t)t * H + hb + h0) = v;
        }
    }
}

// ---------------- recurrence: 8-CTA cluster, DSMEM spike broadcast ----------------
// Each CTA owns 512 neurons (128 words). Thread pairs share one word and split
// the spike list by parity (combined via shfl_xor). Spikes are written into
// every CTA's per-rank smem region via st.shared::cluster; one cluster barrier
// per step publishes lists + counts (release/acquire).
__global__ void __cluster_dims__(CSZ, 1, 1) __launch_bounds__(THR, 1)
snn_recur_cluster(void* __restrict__ out) {
    __shared__ int listbuf[2][CSZ][REG];
    __shared__ int cnt_arr[2][CSZ];
    __shared__ int c2[2];

    const int tid = threadIdx.x;
    const int rank = blockIdx.x;          // single cluster: blockIdx == ctarank
    const int wl = tid >> 1;              // local word 0..127
    const int par = tid & 1;              // spike-list parity
    const int wglob = rank * WPC + wl;    // global word
    const int h0 = wglob << 2;            // first neuron id of this word
    const bool ro_warp = (rank == CSZ - 1) && (tid >= THR - 32);
    const int ro_lane = tid - (THR - 32);

    int mem0 = 0, mem1 = 0, mem2 = 0, mem3 = 0;
    int syn0 = 0, syn1 = 0, syn2 = 0, syn3 = 0;
    int sp0 = 0, sp1 = 0, sp2 = 0, sp3 = 0;
    int rm = 0, rs = 0;

    if (tid < CSZ) { cnt_arr[0][tid] = 0; cnt_arr[1][tid] = 0; }
    if (tid == 0) { c2[0] = 0; c2[1] = 0; }
    __syncthreads();
    // all CTAs initialized before any remote traffic
    asm volatile("barrier.cluster.arrive.aligned;" ::: "memory");
    asm volatile("barrier.cluster.wait.aligned;" ::: "memory");

    int4 ic = *(const int4*)(g_in + h0);   // in-current for t=0

    for (int t = 0; t < T; t++) {
        const int p = t & 1, pn = p ^ 1;

        // ---- readout for step t-1 (one warp, overlapped with gather) ----
        if (ro_warp && t > 0) {
            int ro = 0;
            for (int r = 0; r < CSZ; r++) {
                int nr = cnt_arr[p][r];
                for (int j = 0; j < nr; j++) {
                    int k = listbuf[p][r][j];
                    ro += (int)g_w2T[(k << 5) + ro_lane];
                }
            }
            rm = rm - (rm >> 3) + rs;
            rs = rs - (rs >> 4) + ro;
            if (ro_lane < O) store_out(out, ro_lane * T + (t - 1), rm);
        }

        // ---- recurrent feedback gather (parity-split across thread pairs) ----
        int fb0 = 0, fb1 = 0, fb2 = 0, fb3 = 0;
        for (int r = 0; r < CSZ; r++) {
            int nr = cnt_arr[p][r];
            for (int j = par; j < nr; j += 2) {
                int k = listbuf[p][r][j];
                int v = *(const int*)(g_v1T + ((size_t)k << 12) + (wglob << 2));
                fb0 = __dp4a(v, 0x00000001, fb0);
                fb1 = __dp4a(v, 0x00000100, fb1);
                fb2 = __dp4a(v, 0x00010000, fb2);
                fb3 = __dp4a(v, 0x01000000, fb3);
            }
        }
        fb0 += __shfl_xor_sync(0xffffffffu, fb0, 1);
        fb1 += __shfl_xor_sync(0xffffffffu, fb1, 1);
        fb2 += __shfl_xor_sync(0xffffffffu, fb2, 1);
        fb3 += __shfl_xor_sync(0xffffffffu, fb3, 1);

        // ---- LIF + spike publish (even thread of each pair) ----
        if (par == 0) {
            int m, ns0, ns1, ns2, ns3;
            m = sp0 ? 0 : mem0; ns0 = m > 1; mem0 = m - (m >> 3) + syn0; syn0 = syn0 - (syn0 >> 4) + ic.x + fb0;
            m = sp1 ? 0 : mem1; ns1 = m > 1; mem1 = m - (m >> 3) + syn1; syn1 = syn1 - (syn1 >> 4) + ic.y + fb1;
            m = sp2 ? 0 : mem2; ns2 = m > 1; mem2 = m - (m >> 3) + syn2; syn2 = syn2 - (syn2 >> 4) + ic.z + fb2;
            m = sp3 ? 0 : mem3; ns3 = m > 1; mem3 = m - (m >> 3) + syn3; syn3 = syn3 - (syn3 >> 4) + ic.w + fb3;

            int nl = ns0 + ns1 + ns2 + ns3;
            if (nl) {
                int pos = atomicAdd(&c2[pn], nl);
                int vals[4]; int q = 0;
                if (ns0) vals[q++] = h0;
                if (ns1) vals[q++] = h0 + 1;
                if (ns2) vals[q++] = h0 + 2;
                if (ns3) vals[q++] = h0 + 3;
                uint32_t base = (uint32_t)__cvta_generic_to_shared(&listbuf[pn][rank][pos]);
                for (int i = 0; i < nl; i++)
                    for (int rr = 0; rr < CSZ; rr++)
                        st_remote(base + (uint32_t)(i * 4), (uint32_t)rr, vals[i]);
            }
            sp0 = ns0; sp1 = ns1; sp2 = ns2; sp3 = ns3;
        }

        __syncthreads();                 // local atomics final, remote stores issued
        if (tid == 0) {
            int cn = c2[pn];
            c2[pn] = 0;                  // ready for reuse at step t+2
            uint32_t a = (uint32_t)__cvta_generic_to_shared(&cnt_arr[pn][rank]);
            for (int rr = 0; rr < CSZ; rr++) st_remote(a, (uint32_t)rr, cn);
        }
        // prefetch next step's input current; hides L2 latency behind the barrier
        int tn = (t + 1 < T) ? (t + 1) : t;
        ic = *(const int4*)(g_in + (size_t)tn * H + h0);

        asm volatile("barrier.cluster.arrive.aligned;" ::: "memory");
        asm volatile("barrier.cluster.wait.aligned;" ::: "memory");
    }

    // ---- epilogue: readout for t = T-1 (ro_cur of last step only affects rs) ----
    if (ro_warp) {
        rm = rm - (rm >> 3) + rs;
        if (ro_lane < O) store_out(out, ro_lane * T + (T - 1), rm);
    }
}

// ---------------- launcher ----------------
extern "C" void kernel_launch(void* const* d_in, const int* in_sizes, int n_in,
                              void* d_out, int out_size) {
    // Identify inputs by element count (order-independent; all sizes unique).
    const void *spk = 0, *w1 = 0, *v1 = 0, *w2 = 0;
    for (int i = 0; i < n_in; i++) {
        switch (in_sizes[i]) {
            case T * NI:  spk = d_in[i]; break;   // 700,000
            case H * NI:  w1  = d_in[i]; break;   // 2,867,200
            case H * H:   v1  = d_in[i]; break;   // 16,777,216
            case O * H:   w2  = d_in[i]; break;   // 81,920
        }
    }

    detect_dtype_kernel<<<1, 1>>>(w1);

    pack_w1_kernel<<<(H * NIP + 255) / 256, 256>>>(w1);
    pack_sp_kernel<<<(T * NIP + 255) / 256, 256>>>(spk);
    pack_w2_kernel<<<(H * 32 + 255) / 256, 256>>>(w2);
    dim3 gtr(H / 64, H / 64);
    pack_v1T_kernel<<<gtr, 256>>>(v1);

    dim3 gg(H / 32, (T + 31) / 32);
    gemm_in_kernel<<<gg, 64>>>();

    snn_recur_cluster<<<CSZ, THR>>>(d_out);
}

// round 7
// speedup vs baseline: 3.3580x; 3.3580x over previous
#include <cuda_runtime.h>
#include <stdint.h>
#include <math.h>

#define NI 700
#define NIP 704
#define H 4096
#define T 1000
#define O 20
#define KC (NIP/4)   // 176 u32 chunks per row
#define KPAD 177

// ---------------- scratch (static device memory; no allocs) ----------------
__device__ __align__(16) int8_t g_w1p[H * NIP];        // w1 packed int8, padded 700->704
__device__ __align__(16) int8_t g_sp [T * NIP];        // spikes packed int8 (0/1), padded
__device__ __align__(16) int8_t g_v1T[(size_t)H * H];  // v1T[k][h] = v1[h][k], int8
__device__ __align__(16) int8_t g_w2T[H * 32];         // w2T[k][o], padded 20->32
__device__ __align__(16) int    g_in [T * H];          // in_all[t][h], int32 (exact)
__device__ int g_mode;  // input dtype: 0=int64, 1=int32, 2=float32, 3=float64

// ---------------- input dtype probe (on w1: dense values in [-8,7]) ----------------
__global__ void detect_dtype_kernel(const void* __restrict__ p) {
    const int* w = (const int*)p;
    bool i64 = true;
    for (int i = 0; i < 8; i++) {
        int lo = w[2 * i], hi = w[2 * i + 1];
        if (!(lo >= -8 && lo <= 7 && hi == (lo < 0 ? -1 : 0))) i64 = false;
    }
    if (i64) { g_mode = 0; return; }
    bool i32 = true;
    for (int i = 0; i < 16; i++) {
        int v = w[i];
        if (!(v >= -8 && v <= 7)) i32 = false;
    }
    if (i32) { g_mode = 1; return; }
    bool f32 = true;
    for (int i = 0; i < 16; i++) {
        float f = __int_as_float(w[i]);
        if (!(isfinite(f) && fabsf(f) <= 8.0f && f == truncf(f))) f32 = false;
    }
    if (f32) { g_mode = 2; return; }
    g_mode = 3;  // float64
}

__device__ __forceinline__ int load_elem(const void* p, long idx) {
    switch (g_mode) {
        case 0:  return (int)((const long long*)p)[idx];
        case 1:  return ((const int*)p)[idx];
        case 2:  return (int)((const float*)p)[idx];
        default: return (int)((const double*)p)[idx];
    }
}

// ---------------- pack kernels ----------------
__global__ void pack_w1_kernel(const void* __restrict__ w1) {
    int idx = blockIdx.x * blockDim.x + threadIdx.x;
    if (idx >= H * NIP) return;
    int h = idx / NIP, c = idx - h * NIP;
    g_w1p[idx] = (c < NI) ? (int8_t)load_elem(w1, (long)h * NI + c) : (int8_t)0;
}

__global__ void pack_sp_kernel(const void* __restrict__ spk) {
    int idx = blockIdx.x * blockDim.x + threadIdx.x;
    if (idx >= T * NIP) return;
    int t = idx / NIP, c = idx - t * NIP;
    g_sp[idx] = (c < NI) ? (int8_t)load_elem(spk, (long)t * NI + c) : (int8_t)0;
}

__global__ void pack_w2_kernel(const void* __restrict__ w2) {
    int idx = blockIdx.x * blockDim.x + threadIdx.x;
    if (idx >= H * 32) return;
    int k = idx >> 5, o = idx & 31;
    g_w2T[idx] = (o < O) ? (int8_t)load_elem(w2, (long)o * H + k) : (int8_t)0;
}

// tiled transpose: v1[h][k] -> g_v1T[k][h] (int8)
__global__ void pack_v1T_kernel(const void* __restrict__ v1) {
    __shared__ int8_t tile[64][65];
    int kb = blockIdx.x * 64;
    int hb = blockIdx.y * 64;
    for (int i = threadIdx.x; i < 64 * 64; i += 256) {
        int r = i >> 6, c = i & 63;          // r = h-local, c = k-local
        tile[c][r] = (int8_t)load_elem(v1, (long)(hb + r) * H + (kb + c));
    }
    __syncthreads();
    for (int i = threadIdx.x; i < 64 * 64; i += 256) {
        int r = i >> 6, c = i & 63;          // r = k-local, c = h-local
        g_v1T[(size_t)(kb + r) * H + (hb + c)] = tile[r][c];
    }
}

// ---------------- feed-forward GEMM: in_all[t][h] = sum_i w1[h][i]*spk[t][i] ----------------
__global__ void gemm_in_kernel() {
    __shared__ int swt[32 * KPAD];
    __shared__ int sst[32 * KPAD];
    const int tid = threadIdx.x;
    const int hb = blockIdx.x * 32;
    const int tb = blockIdx.y * 32;
    const int* w32 = (const int*)g_w1p;
    const int* s32 = (const int*)g_sp;

    for (int i = tid; i < 32 * KC; i += 64) {
        int r = i / KC, c = i - r * KC;
        swt[r * KPAD + c] = w32[(hb + r) * KC + c];
    }
    for (int i = tid; i < 32 * KC; i += 64) {
        int r = i / KC, c = i - r * KC;
        int t = tb + r;
        sst[r * KPAD + c] = (t < T) ? s32[t * KC + c] : 0;
    }
    __syncthreads();

    const int h0 = (tid >> 3) * 4;   // 0..28
    const int t0 = (tid & 7) * 4;    // 0..28
    int acc[4][4];
#pragma unroll
    for (int i = 0; i < 4; i++)
#pragma unroll
        for (int j = 0; j < 4; j++) acc[i][j] = 0;

    const int* wp = &swt[h0 * KPAD];
    const int* sp = &sst[t0 * KPAD];
    for (int c = 0; c < KC; c++) {
        int w0 = wp[c], w1v = wp[KPAD + c], w2v = wp[2 * KPAD + c], w3v = wp[3 * KPAD + c];
        int s0 = sp[c], s1 = sp[KPAD + c], s2 = sp[2 * KPAD + c], s3 = sp[3 * KPAD + c];
        acc[0][0] = __dp4a(w0, s0, acc[0][0]); acc[0][1] = __dp4a(w0, s1, acc[0][1]);
        acc[0][2] = __dp4a(w0, s2, acc[0][2]); acc[0][3] = __dp4a(w0, s3, acc[0][3]);
        acc[1][0] = __dp4a(w1v, s0, acc[1][0]); acc[1][1] = __dp4a(w1v, s1, acc[1][1]);
        acc[1][2] = __dp4a(w1v, s2, acc[1][2]); acc[1][3] = __dp4a(w1v, s3, acc[1][3]);
        acc[2][0] = __dp4a(w2v, s0, acc[2][0]); acc[2][1] = __dp4a(w2v, s1, acc[2][1]);
        acc[2][2] = __dp4a(w2v, s2, acc[2][2]); acc[2][3] = __dp4a(w2v, s3, acc[2][3]);
        acc[3][0] = __dp4a(w3v, s0, acc[3][0]); acc[3][1] = __dp4a(w3v, s1, acc[3][1]);
        acc[3][2] = __dp4a(w3v, s2, acc[3][2]); acc[3][3] = __dp4a(w3v, s3, acc[3][3]);
    }
#pragma unroll
    for (int ti = 0; ti < 4; ti++) {
        int t = tb + t0 + ti;
        if (t < T) {
            int4 v = make_int4(acc[0][ti], acc[1][ti], acc[2][ti], acc[3][ti]);
            *(int4*)(g_in + (size_t)t * H + hb + h0) = v;
        }
    }
}

// 4x4 byte transpose of (a,b,c,d) + dp4a-sum into 4 accumulators:
// A_i += a_i + b_i + c_i + d_i  (signed bytes; exact integer sums)
#define QUAD4(a, b, c, d, A0, A1, A2, A3) do {                                 \
    unsigned lab = __byte_perm((unsigned)(a), (unsigned)(b), 0x5140);          \
    unsigned hab = __byte_perm((unsigned)(a), (unsigned)(b), 0x7362);          \
    unsigned lcd = __byte_perm((unsigned)(c), (unsigned)(d), 0x5140);          \
    unsigned hcd = __byte_perm((unsigned)(c), (unsigned)(d), 0x7362);          \
    (A0) = __dp4a((int)__byte_perm(lab, lcd, 0x5410), 0x01010101, (A0));       \
    (A1) = __dp4a((int)__byte_perm(lab, lcd, 0x7632), 0x01010101, (A1));       \
    (A2) = __dp4a((int)__byte_perm(hab, hcd, 0x5410), 0x01010101, (A2));       \
    (A3) = __dp4a((int)__byte_perm(hab, hcd, 0x7632), 0x01010101, (A3));       \
} while (0)

// LIF update for one neuron (constant index i at expansion site)
#define LIF1(i, icval) do {                                                    \
    int m = ((spm >> (i)) & 1u) ? 0 : mem[i];                                  \
    nm |= (unsigned)(m > 1) << (i);                                            \
    mem[i] = m - (m >> 3) + syn[i];                                            \
    syn[i] = syn[i] - (syn[i] >> 4) + (icval) + acc[i];                        \
} while (0)

// ---------------- sequential recurrence: one persistent CTA, 288 threads ----
// Threads 0..255: gather+LIF, 16 neurons each (state + fb in registers).
// One LDG.128 per spike row; spike quads combined via PRMT byte-transpose so
// each dp4a sums 4 spike contributions. Warp 8 (tid 256..287): readout.
// One __syncthreads per step.
__global__ void __launch_bounds__(288, 1) snn_recur_kernel(void* __restrict__ out) {
    __shared__ int listbuf[2][H];
    __shared__ int cnts[T + 1];
    const int tid = threadIdx.x;
    const bool gth = tid < 256;
    const int h0 = tid << 4;             // first neuron (also row byte offset)
    const int ro_lane = tid - 256;

    int mem[16], syn[16], acc[16];
    unsigned spm = 0;                    // previous-step spike bitmask
    int rm = 0, rs = 0;                  // readout state
#pragma unroll
    for (int i = 0; i < 16; i++) { mem[i] = 0; syn[i] = 0; }

    for (int i = tid; i <= T; i += 288) cnts[i] = 0;
    __syncthreads();

    for (int t = 0; t < T; t++) {
        const int p = t & 1, pn = p ^ 1;
        const int n = cnts[t];           // spikes produced at step t-1
        const int* lb = listbuf[p];

        if (gth) {
            // prefetch this step's input currents (hidden behind the gather)
            const int4* gi = (const int4*)(g_in + (size_t)t * H + h0);
            int4 ic0 = __ldg(gi + 0), ic1 = __ldg(gi + 1);
            int4 ic2 = __ldg(gi + 2), ic3 = __ldg(gi + 3);

#pragma unroll
            for (int i = 0; i < 16; i++) acc[i] = 0;

            const int8_t* vbase = g_v1T + h0;
            int j = 0;
            for (; j + 4 <= n; j += 4) {
                int k0 = lb[j], k1 = lb[j + 1], k2 = lb[j + 2], k3 = lb[j + 3];
                int4 A = *(const int4*)(vbase + ((size_t)k0 << 12));
                int4 B = *(const int4*)(vbase + ((size_t)k1 << 12));
                int4 C = *(const int4*)(vbase + ((size_t)k2 << 12));
                int4 D = *(const int4*)(vbase + ((size_t)k3 << 12));
                QUAD4(A.x, B.x, C.x, D.x, acc[0],  acc[1],  acc[2],  acc[3]);
                QUAD4(A.y, B.y, C.y, D.y, acc[4],  acc[5],  acc[6],  acc[7]);
                QUAD4(A.z, B.z, C.z, D.z, acc[8],  acc[9],  acc[10], acc[11]);
                QUAD4(A.w, B.w, C.w, D.w, acc[12], acc[13], acc[14], acc[15]);
            }
            for (; j < n; j++) {         // tail (0..3 spikes)
                int4 V = *(const int4*)(vbase + ((size_t)lb[j] << 12));
                acc[0]  = __dp4a(V.x, 0x00000001, acc[0]);
                acc[1]  = __dp4a(V.x, 0x00000100, acc[1]);
                acc[2]  = __dp4a(V.x, 0x00010000, acc[2]);
                acc[3]  = __dp4a(V.x, 0x01000000, acc[3]);
                acc[4]  = __dp4a(V.y, 0x00000001, acc[4]);
                acc[5]  = __dp4a(V.y, 0x00000100, acc[5]);
                acc[6]  = __dp4a(V.y, 0x00010000, acc[6]);
                acc[7]  = __dp4a(V.y, 0x01000000, acc[7]);
                acc[8]  = __dp4a(V.z, 0x00000001, acc[8]);
                acc[9]  = __dp4a(V.z, 0x00000100, acc[9]);
                acc[10] = __dp4a(V.z, 0x00010000, acc[10]);
                acc[11] = __dp4a(V.z, 0x01000000, acc[11]);
                acc[12] = __dp4a(V.w, 0x00000001, acc[12]);
                acc[13] = __dp4a(V.w, 0x00000100, acc[13]);
                acc[14] = __dp4a(V.w, 0x00010000, acc[14]);
                acc[15] = __dp4a(V.w, 0x01000000, acc[15]);
            }

            // ---- LIF (reset by prev spike -> threshold -> decay/integrate) ----
            unsigned nm = 0;
            LIF1(0,  ic0.x); LIF1(1,  ic0.y); LIF1(2,  ic0.z); LIF1(3,  ic0.w);
            LIF1(4,  ic1.x); LIF1(5,  ic1.y); LIF1(6,  ic1.z); LIF1(7,  ic1.w);
            LIF1(8,  ic2.x); LIF1(9,  ic2.y); LIF1(10, ic2.z); LIF1(11, ic2.w);
            LIF1(12, ic3.x); LIF1(13, ic3.y); LIF1(14, ic3.z); LIF1(15, ic3.w);

            // ---- append new spikes ----
            int c = __popc(nm);
            if (c) {
                int pos = atomicAdd(&cnts[t + 1], c);
                unsigned b = nm;
                while (b) {
                    int i = __ffs(b) - 1;
                    b &= b - 1;
                    listbuf[pn][pos++] = h0 + i;
                }
            }
            spm = nm;
        } else if (t > 0) {
            // ---- readout for step t-1 (warp 8, overlapped with gather) ----
            int ro = 0;
            for (int j = 0; j < n; j++)
                ro += (int)g_w2T[(lb[j] << 5) + ro_lane];
            rm = rm - (rm >> 3) + rs;
            rs = rs - (rs >> 4) + ro;
            if (ro_lane < O) ((float*)out)[ro_lane * T + (t - 1)] = (float)rm;
        }

        __syncthreads();                 // publish listbuf[pn] + cnts[t+1]
    }

    // ---- epilogue: readout for t = T-1 (no gather needed) ----
    if (!gth) {
        rm = rm - (rm >> 3) + rs;
        if (ro_lane < O) ((float*)out)[ro_lane * T + (T - 1)] = (float)rm;
    }
}

// ---------------- launcher ----------------
extern "C" void kernel_launch(void* const* d_in, const int* in_sizes, int n_in,
                              void* d_out, int out_size) {
    // Identify inputs by element count (order-independent; all sizes unique).
    const void *spk = 0, *w1 = 0, *v1 = 0, *w2 = 0;
    for (int i = 0; i < n_in; i++) {
        switch (in_sizes[i]) {
            case T * NI:  spk = d_in[i]; break;   // 700,000
            case H * NI:  w1  = d_in[i]; break;   // 2,867,200
            case H * H:   v1  = d_in[i]; break;   // 16,777,216
            case O * H:   w2  = d_in[i]; break;   // 81,920
        }
    }

    detect_dtype_kernel<<<1, 1>>>(w1);

    pack_w1_kernel<<<(H * NIP + 255) / 256, 256>>>(w1);
    pack_sp_kernel<<<(T * NIP + 255) / 256, 256>>>(spk);
    pack_w2_kernel<<<(H * 32 + 255) / 256, 256>>>(w2);
    dim3 gtr(H / 64, H / 64);
    pack_v1T_kernel<<<gtr, 256>>>(v1);

    dim3 gg(H / 32, (T + 31) / 32);
    gemm_in_kernel<<<gg, 64>>>();

    snn_recur_kernel<<<1, 288>>>(d_out);
}

// round 8
// speedup vs baseline: 3.5277x; 1.0505x over previous
#include <cuda_runtime.h>
#include <stdint.h>
#include <math.h>

#define NI 700
#define NIP 704
#define H 4096
#define T 1000
#define O 20
#define KC (NIP/4)   // 176 u32 chunks per row
#define KPAD 177

// ---------------- scratch (static device memory; no allocs) ----------------
__device__ __align__(16) int8_t  g_w1p[H * NIP];        // w1 packed int8, padded 700->704
__device__ __align__(16) int8_t  g_sp [T * NIP];        // spikes packed int8 (0/1), padded
__device__ __align__(16) uint8_t g_v1B[(size_t)H * H];  // v1B[k][h] = v1[h][k] + 8  (0..15)
__device__ __align__(16) int8_t  g_w2T[H * 32];         // w2T[k][o], padded 20->32
__device__ __align__(16) int     g_in [T * H];          // in_all[t][h], int32 (exact)
__device__ int g_mode;  // input dtype: 0=int64, 1=int32, 2=float32, 3=float64

// ---------------- input dtype probe (on w1: dense values in [-8,7]) ----------------
__global__ void detect_dtype_kernel(const void* __restrict__ p) {
    const int* w = (const int*)p;
    bool i64 = true;
    for (int i = 0; i < 8; i++) {
        int lo = w[2 * i], hi = w[2 * i + 1];
        if (!(lo >= -8 && lo <= 7 && hi == (lo < 0 ? -1 : 0))) i64 = false;
    }
    if (i64) { g_mode = 0; return; }
    bool i32 = true;
    for (int i = 0; i < 16; i++) {
        int v = w[i];
        if (!(v >= -8 && v <= 7)) i32 = false;
    }
    if (i32) { g_mode = 1; return; }
    bool f32 = true;
    for (int i = 0; i < 16; i++) {
        float f = __int_as_float(w[i]);
        if (!(isfinite(f) && fabsf(f) <= 8.0f && f == truncf(f))) f32 = false;
    }
    if (f32) { g_mode = 2; return; }
    g_mode = 3;  // float64
}

__device__ __forceinline__ int load_elem(const void* p, long idx) {
    switch (g_mode) {
        case 0:  return (int)((const long long*)p)[idx];
        case 1:  return ((const int*)p)[idx];
        case 2:  return (int)((const float*)p)[idx];
        default: return (int)((const double*)p)[idx];
    }
}

// ---------------- pack kernels ----------------
__global__ void pack_w1_kernel(const void* __restrict__ w1) {
    int idx = blockIdx.x * blockDim.x + threadIdx.x;
    if (idx >= H * NIP) return;
    int h = idx / NIP, c = idx - h * NIP;
    g_w1p[idx] = (c < NI) ? (int8_t)load_elem(w1, (long)h * NI + c) : (int8_t)0;
}

__global__ void pack_sp_kernel(const void* __restrict__ spk) {
    int idx = blockIdx.x * blockDim.x + threadIdx.x;
    if (idx >= T * NIP) return;
    int t = idx / NIP, c = idx - t * NIP;
    g_sp[idx] = (c < NI) ? (int8_t)load_elem(spk, (long)t * NI + c) : (int8_t)0;
}

__global__ void pack_w2_kernel(const void* __restrict__ w2) {
    int idx = blockIdx.x * blockDim.x + threadIdx.x;
    if (idx >= H * 32) return;
    int k = idx >> 5, o = idx & 31;
    g_w2T[idx] = (o < O) ? (int8_t)load_elem(w2, (long)o * H + k) : (int8_t)0;
}

// tiled transpose: v1[h][k] -> g_v1B[k][h] = v1[h][k] + 8 (biased uint8)
__global__ void pack_v1T_kernel(const void* __restrict__ v1) {
    __shared__ uint8_t tile[64][65];
    int kb = blockIdx.x * 64;
    int hb = blockIdx.y * 64;
    for (int i = threadIdx.x; i < 64 * 64; i += 256) {
        int r = i >> 6, c = i & 63;          // r = h-local, c = k-local
        tile[c][r] = (uint8_t)(load_elem(v1, (long)(hb + r) * H + (kb + c)) + 8);
    }
    __syncthreads();
    for (int i = threadIdx.x; i < 64 * 64; i += 256) {
        int r = i >> 6, c = i & 63;          // r = k-local, c = h-local
        g_v1B[(size_t)(kb + r) * H + (hb + c)] = tile[r][c];
    }
}

// ---------------- feed-forward GEMM: in_all[t][h] = sum_i w1[h][i]*spk[t][i] ----------------
__global__ void gemm_in_kernel() {
    __shared__ int swt[32 * KPAD];
    __shared__ int sst[32 * KPAD];
    const int tid = threadIdx.x;
    const int hb = blockIdx.x * 32;
    const int tb = blockIdx.y * 32;
    const int* w32 = (const int*)g_w1p;
    const int* s32 = (const int*)g_sp;

    for (int i = tid; i < 32 * KC; i += 64) {
        int r = i / KC, c = i - r * KC;
        swt[r * KPAD + c] = w32[(hb + r) * KC + c];
    }
    for (int i = tid; i < 32 * KC; i += 64) {
        int r = i / KC, c = i - r * KC;
        int t = tb + r;
        sst[r * KPAD + c] = (t < T) ? s32[t * KC + c] : 0;
    }
    __syncthreads();

    const int h0 = (tid >> 3) * 4;   // 0..28
    const int t0 = (tid & 7) * 4;    // 0..28
    int acc[4][4];
#pragma unroll
    for (int i = 0; i < 4; i++)
#pragma unroll
        for (int j = 0; j < 4; j++) acc[i][j] = 0;

    const int* wp = &swt[h0 * KPAD];
    const int* sp = &sst[t0 * KPAD];
    for (int c = 0; c < KC; c++) {
        int w0 = wp[c], w1v = wp[KPAD + c], w2v = wp[2 * KPAD + c], w3v = wp[3 * KPAD + c];
        int s0 = sp[c], s1 = sp[KPAD + c], s2 = sp[2 * KPAD + c], s3 = sp[3 * KPAD + c];
        acc[0][0] = __dp4a(w0, s0, acc[0][0]); acc[0][1] = __dp4a(w0, s1, acc[0][1]);
        acc[0][2] = __dp4a(w0, s2, acc[0][2]); acc[0][3] = __dp4a(w0, s3, acc[0][3]);
        acc[1][0] = __dp4a(w1v, s0, acc[1][0]); acc[1][1] = __dp4a(w1v, s1, acc[1][1]);
        acc[1][2] = __dp4a(w1v, s2, acc[1][2]); acc[1][3] = __dp4a(w1v, s3, acc[1][3]);
        acc[2][0] = __dp4a(w2v, s0, acc[2][0]); acc[2][1] = __dp4a(w2v, s1, acc[2][1]);
        acc[2][2] = __dp4a(w2v, s2, acc[2][2]); acc[2][3] = __dp4a(w2v, s3, acc[2][3]);
        acc[3][0] = __dp4a(w3v, s0, acc[3][0]); acc[3][1] = __dp4a(w3v, s1, acc[3][1]);
        acc[3][2] = __dp4a(w3v, s2, acc[3][2]); acc[3][3] = __dp4a(w3v, s3, acc[3][3]);
    }
#pragma unroll
    for (int ti = 0; ti < 4; ti++) {
        int t = tb + t0 + ti;
        if (t < T) {
            int4 v = make_int4(acc[0][ti], acc[1][ti], acc[2][ti], acc[3][ti]);
            *(int4*)(g_in + (size_t)t * H + hb + h0) = v;
        }
    }
}

// LIF update for one neuron (constant index i at expansion site).
// fb_i = (int)accu[i] - bias  (bias = 8*n, exact unbias of byte-packed sums)
#define LIF1(i, icval) do {                                                    \
    int m = ((spm >> (i)) & 1u) ? 0 : mem[i];                                  \
    nm |= (unsigned)(m > 1) << (i);                                            \
    mem[i] = m - (m >> 3) + syn[i];                                            \
    syn[i] = syn[i] - (syn[i] >> 4) + (icval) + (int)accu[i] - bias;           \
} while (0)

// ---------------- sequential recurrence: one persistent CTA, 288 threads ----
// Threads 0..255: gather+LIF, 16 neurons each. Recurrent weights stored as
// biased bytes (w+8, 0..15); <=16 spike rows are summed per byte lane with
// plain 32-bit adds (max 240 < 256, no carry), then unpacked with unsigned
// dp4a byte-selects; uniform bias 8n removed at the end. One LDG.128 + 4 IADD
// per spike per thread. Warp 8 (tid 256..287): readout. One barrier per step.
__global__ void __launch_bounds__(288, 1) snn_recur_kernel(void* __restrict__ out) {
    __shared__ int listbuf[2][H];
    __shared__ int cnts[T + 1];
    const int tid = threadIdx.x;
    const bool gth = tid < 256;
    const int h0 = tid << 4;             // first neuron (also row byte offset)
    const int ro_lane = tid - 256;

    int mem[16], syn[16];
    unsigned accu[16];
    unsigned spm = 0;                    // previous-step spike bitmask
    int rm = 0, rs = 0;                  // readout state
#pragma unroll
    for (int i = 0; i < 16; i++) { mem[i] = 0; syn[i] = 0; }

    for (int i = tid; i <= T; i += 288) cnts[i] = 0;
    __syncthreads();

    for (int t = 0; t < T; t++) {
        const int p = t & 1, pn = p ^ 1;
        const int n = cnts[t];           // spikes produced at step t-1
        const int* lb = listbuf[p];

        if (gth) {
            // prefetch this step's input currents (hidden behind the gather)
            const int4* gi = (const int4*)(g_in + (size_t)t * H + h0);
            int4 ic0 = __ldg(gi + 0), ic1 = __ldg(gi + 1);
            int4 ic2 = __ldg(gi + 2), ic3 = __ldg(gi + 3);

#pragma unroll
            for (int i = 0; i < 16; i++) accu[i] = 0;

            const uint8_t* vbase = g_v1B + h0;
            int j = 0;
            while (j < n) {
                int e = j + 16; if (e > n) e = n;     // chunk of <=16 rows
                unsigned pa = 0, pb = 0, pc = 0, pd = 0;
                for (; j < e; j++) {
                    uint4 R = *(const uint4*)(vbase + ((size_t)lb[j] << 12));
                    pa += R.x; pb += R.y; pc += R.z; pd += R.w;
                }
                accu[0]  = __dp4a(pa, 0x00000001u, accu[0]);
                accu[1]  = __dp4a(pa, 0x00000100u, accu[1]);
                accu[2]  = __dp4a(pa, 0x00010000u, accu[2]);
                accu[3]  = __dp4a(pa, 0x01000000u, accu[3]);
                accu[4]  = __dp4a(pb, 0x00000001u, accu[4]);
                accu[5]  = __dp4a(pb, 0x00000100u, accu[5]);
                accu[6]  = __dp4a(pb, 0x00010000u, accu[6]);
                accu[7]  = __dp4a(pb, 0x01000000u, accu[7]);
                accu[8]  = __dp4a(pc, 0x00000001u, accu[8]);
                accu[9]  = __dp4a(pc, 0x00000100u, accu[9]);
                accu[10] = __dp4a(pc, 0x00010000u, accu[10]);
                accu[11] = __dp4a(pc, 0x01000000u, accu[11]);
                accu[12] = __dp4a(pd, 0x00000001u, accu[12]);
                accu[13] = __dp4a(pd, 0x00000100u, accu[13]);
                accu[14] = __dp4a(pd, 0x00010000u, accu[14]);
                accu[15] = __dp4a(pd, 0x01000000u, accu[15]);
            }
            const int bias = n * 8;

            // ---- LIF (reset by prev spike -> threshold -> decay/integrate) ----
            unsigned nm = 0;
            LIF1(0,  ic0.x); LIF1(1,  ic0.y); LIF1(2,  ic0.z); LIF1(3,  ic0.w);
            LIF1(4,  ic1.x); LIF1(5,  ic1.y); LIF1(6,  ic1.z); LIF1(7,  ic1.w);
            LIF1(8,  ic2.x); LIF1(9,  ic2.y); LIF1(10, ic2.z); LIF1(11, ic2.w);
            LIF1(12, ic3.x); LIF1(13, ic3.y); LIF1(14, ic3.z); LIF1(15, ic3.w);

            // ---- append new spikes ----
            int c = __popc(nm);
            if (c) {
                int pos = atomicAdd(&cnts[t + 1], c);
                unsigned b = nm;
                while (b) {
                    int i = __ffs(b) - 1;
                    b &= b - 1;
                    listbuf[pn][pos++] = h0 + i;
                }
            }
            spm = nm;
        } else if (t > 0) {
            // ---- readout for step t-1 (warp 8, overlapped with gather) ----
            int ro = 0;
            for (int j = 0; j < n; j++)
                ro += (int)g_w2T[(lb[j] << 5) + ro_lane];
            rm = rm - (rm >> 3) + rs;
            rs = rs - (rs >> 4) + ro;
            if (ro_lane < O) ((float*)out)[ro_lane * T + (t - 1)] = (float)rm;
        }

        __syncthreads();                 // publish listbuf[pn] + cnts[t+1]
    }

    // ---- epilogue: readout for t = T-1 (no gather needed) ----
    if (!gth) {
        rm = rm - (rm >> 3) + rs;
        if (ro_lane < O) ((float*)out)[ro_lane * T + (T - 1)] = (float)rm;
    }
}

// ---------------- launcher ----------------
extern "C" void kernel_launch(void* const* d_in, const int* in_sizes, int n_in,
                              void* d_out, int out_size) {
    // Identify inputs by element count (order-independent; all sizes unique).
    const void *spk = 0, *w1 = 0, *v1 = 0, *w2 = 0;
    for (int i = 0; i < n_in; i++) {
        switch (in_sizes[i]) {
            case T * NI:  spk = d_in[i]; break;   // 700,000
            case H * NI:  w1  = d_in[i]; break;   // 2,867,200
            case H * H:   v1  = d_in[i]; break;   // 16,777,216
            case O * H:   w2  = d_in[i]; break;   // 81,920
        }
    }

    detect_dtype_kernel<<<1, 1>>>(w1);

    pack_w1_kernel<<<(H * NIP + 255) / 256, 256>>>(w1);
    pack_sp_kernel<<<(T * NIP + 255) / 256, 256>>>(spk);
    pack_w2_kernel<<<(H * 32 + 255) / 256, 256>>>(w2);
    dim3 gtr(H / 64, H / 64);
    pack_v1T_kernel<<<gtr, 256>>>(v1);

    dim3 gg(H / 32, (T + 31) / 32);
    gemm_in_kernel<<<gg, 64>>>();

    snn_recur_kernel<<<1, 288>>>(d_out);
}

// round 9
// speedup vs baseline: 3.8082x; 1.0795x over previous
#include <cuda_runtime.h>
#include <stdint.h>
#include <math.h>

#define NI 700
#define NIP 704
#define H 4096
#define T 1000
#define TPAD 1024
#define O 20

// ---------------- scratch (static device memory; no allocs) ----------------
__device__ __align__(16) int8_t  g_w1p[H * NIP];        // w1 packed int8, padded 700->704
__device__ __align__(16) int8_t  g_sp [TPAD * NIP];     // spikes packed int8, padded rows+cols
__device__ __align__(16) uint8_t g_v1B[(size_t)H * H];  // v1B[k][h] = v1[h][k] + 8  (0..15)
__device__ __align__(16) int8_t  g_w2T[H * 32];         // w2T[k][o], padded 20->32
__device__ __align__(16) int     g_in [T * H];          // in_all[t][h], int32 (exact)
__device__ int g_mode;  // input dtype: 0=int64, 1=int32, 2=float32, 3=float64

// ---------------- input dtype probe (on w1: dense values in [-8,7]) ----------------
__global__ void detect_dtype_kernel(const void* __restrict__ p) {
    const int* w = (const int*)p;
    bool i64 = true;
    for (int i = 0; i < 8; i++) {
        int lo = w[2 * i], hi = w[2 * i + 1];
        if (!(lo >= -8 && lo <= 7 && hi == (lo < 0 ? -1 : 0))) i64 = false;
    }
    if (i64) { g_mode = 0; return; }
    bool i32 = true;
    for (int i = 0; i < 16; i++) {
        int v = w[i];
        if (!(v >= -8 && v <= 7)) i32 = false;
    }
    if (i32) { g_mode = 1; return; }
    bool f32 = true;
    for (int i = 0; i < 16; i++) {
        float f = __int_as_float(w[i]);
        if (!(isfinite(f) && fabsf(f) <= 8.0f && f == truncf(f))) f32 = false;
    }
    if (f32) { g_mode = 2; return; }
    g_mode = 3;  // float64
}

__device__ __forceinline__ int load_elem(const void* p, long idx) {
    switch (g_mode) {
        case 0:  return (int)((const long long*)p)[idx];
        case 1:  return ((const int*)p)[idx];
        case 2:  return (int)((const float*)p)[idx];
        default: return (int)((const double*)p)[idx];
    }
}

// ---------------- pack kernels ----------------
__global__ void pack_w1_kernel(const void* __restrict__ w1) {
    int idx = blockIdx.x * blockDim.x + threadIdx.x;
    if (idx >= H * NIP) return;
    int h = idx / NIP, c = idx - h * NIP;
    g_w1p[idx] = (c < NI) ? (int8_t)load_elem(w1, (long)h * NI + c) : (int8_t)0;
}

__global__ void pack_sp_kernel(const void* __restrict__ spk) {
    int idx = blockIdx.x * blockDim.x + threadIdx.x;
    if (idx >= TPAD * NIP) return;
    int t = idx / NIP, c = idx - t * NIP;
    g_sp[idx] = (t < T && c < NI) ? (int8_t)load_elem(spk, (long)t * NI + c) : (int8_t)0;
}

__global__ void pack_w2_kernel(const void* __restrict__ w2) {
    int idx = blockIdx.x * blockDim.x + threadIdx.x;
    if (idx >= H * 32) return;
    int k = idx >> 5, o = idx & 31;
    g_w2T[idx] = (o < O) ? (int8_t)load_elem(w2, (long)o * H + k) : (int8_t)0;
}

// tiled transpose: v1[h][k] -> g_v1B[k][h] = v1[h][k] + 8 (biased uint8)
__global__ void pack_v1T_kernel(const void* __restrict__ v1) {
    __shared__ uint8_t tile[64][65];
    int kb = blockIdx.x * 64;
    int hb = blockIdx.y * 64;
    for (int i = threadIdx.x; i < 64 * 64; i += 256) {
        int r = i >> 6, c = i & 63;          // r = h-local, c = k-local
        tile[c][r] = (uint8_t)(load_elem(v1, (long)(hb + r) * H + (kb + c)) + 8);
    }
    __syncthreads();
    for (int i = threadIdx.x; i < 64 * 64; i += 256) {
        int r = i >> 6, c = i & 63;          // r = k-local, c = h-local
        g_v1B[(size_t)(kb + r) * H + (hb + c)] = tile[r][c];
    }
}

// ---------------- feed-forward GEMM via IMMA tensor cores ----------------
// in_all[t][h] = sum_k g_sp[t][k] * g_w1p[h][k]  (s8 x s8 -> s32, exact)
// Warp tile: 32(t) x 32(h); block 8 warps = 32(t) x 256(h); K loop 22 x 32.
__device__ __forceinline__ void mma16832(int* d, const unsigned* a, const unsigned* b) {
    asm volatile(
        "mma.sync.aligned.m16n8k32.row.col.s32.s8.s8.s32 "
        "{%0,%1,%2,%3},{%4,%5,%6,%7},{%8,%9},{%0,%1,%2,%3};"
        : "+r"(d[0]), "+r"(d[1]), "+r"(d[2]), "+r"(d[3])
        : "r"(a[0]), "r"(a[1]), "r"(a[2]), "r"(a[3]), "r"(b[0]), "r"(b[1]));
}

__global__ void __launch_bounds__(256, 1) gemm_in_imma() {
    const int warp = threadIdx.x >> 5;
    const int lane = threadIdx.x & 31;
    const int gid = lane >> 2;           // group id (0..7)
    const int tig = lane & 3;            // thread-in-group (0..3)
    const int tb = blockIdx.x * 32;      // t-tile base (rows, padded to 1024)
    const int hb = blockIdx.y * 256 + warp * 32;  // h-tile base

    int acc[2][4][4];
#pragma unroll
    for (int mt = 0; mt < 2; mt++)
#pragma unroll
        for (int nt = 0; nt < 4; nt++)
#pragma unroll
            for (int r = 0; r < 4; r++) acc[mt][nt][r] = 0;

    const int8_t* As = g_sp  + (size_t)(tb + gid) * NIP + tig * 4;
    const int8_t* Bs = g_w1p + (size_t)(hb + gid) * NIP + tig * 4;

    for (int kk = 0; kk < NIP; kk += 32) {
        unsigned a[2][4], b[4][2];
#pragma unroll
        for (int mt = 0; mt < 2; mt++) {
            const int8_t* ap = As + (size_t)mt * 16 * NIP + kk;
            a[mt][0] = *(const unsigned*)(ap);
            a[mt][1] = *(const unsigned*)(ap + 8 * NIP);
            a[mt][2] = *(const unsigned*)(ap + 16);
            a[mt][3] = *(const unsigned*)(ap + 8 * NIP + 16);
        }
#pragma unroll
        for (int nt = 0; nt < 4; nt++) {
            const int8_t* bp = Bs + (size_t)nt * 8 * NIP + kk;
            b[nt][0] = *(const unsigned*)(bp);
            b[nt][1] = *(const unsigned*)(bp + 16);
        }
#pragma unroll
        for (int mt = 0; mt < 2; mt++)
#pragma unroll
            for (int nt = 0; nt < 4; nt++)
                mma16832(acc[mt][nt], a[mt], b[nt]);
    }

    // store: c0,c1 -> (row, col..col+1); c2,c3 -> (row+8, same cols)
#pragma unroll
    for (int mt = 0; mt < 2; mt++) {
#pragma unroll
        for (int nt = 0; nt < 4; nt++) {
            int row0 = tb + mt * 16 + gid;
            int col = hb + nt * 8 + tig * 2;
            if (row0 < T)
                *(int2*)(g_in + (size_t)row0 * H + col) =
                    make_int2(acc[mt][nt][0], acc[mt][nt][1]);
            int row1 = row0 + 8;
            if (row1 < T)
                *(int2*)(g_in + (size_t)row1 * H + col) =
                    make_int2(acc[mt][nt][2], acc[mt][nt][3]);
        }
    }
}

// LIF update for one neuron (constant index i at expansion site).
// fb_i = (int)accu[i] - bias  (bias = 8*n, exact unbias of byte-packed sums)
#define LIF1(i, icval) do {                                                    \
    int m = ((spm >> (i)) & 1u) ? 0 : mem[i];                                  \
    nm |= (unsigned)(m > 1) << (i);                                            \
    mem[i] = m - (m >> 3) + syn[i];                                            \
    syn[i] = syn[i] - (syn[i] >> 4) + (icval) + (int)accu[i] - bias;           \
} while (0)

// ---------------- sequential recurrence: one persistent CTA, 288 threads ----
// Threads 0..255: gather+LIF, 16 neurons each. Biased-byte accumulation:
// <=16 rows summed per byte lane with 32-bit adds (max 240 < 256), unpacked
// with unsigned dp4a byte-selects, bias 8n removed exactly. Warp 8: readout.
__global__ void __launch_bounds__(288, 1) snn_recur_kernel(void* __restrict__ out) {
    __shared__ int listbuf[2][H];
    __shared__ int cnts[T + 1];
    const int tid = threadIdx.x;
    const bool gth = tid < 256;
    const int h0 = tid << 4;             // first neuron (also row byte offset)
    const int ro_lane = tid - 256;

    int mem[16], syn[16];
    unsigned accu[16];
    unsigned spm = 0;                    // previous-step spike bitmask
    int rm = 0, rs = 0;                  // readout state
#pragma unroll
    for (int i = 0; i < 16; i++) { mem[i] = 0; syn[i] = 0; }

    for (int i = tid; i <= T; i += 288) cnts[i] = 0;
    __syncthreads();

    for (int t = 0; t < T; t++) {
        const int p = t & 1, pn = p ^ 1;
        const int n = cnts[t];           // spikes produced at step t-1
        const int* lb = listbuf[p];

        if (gth) {
            // prefetch this step's input currents (hidden behind the gather)
            const int4* gi = (const int4*)(g_in + (size_t)t * H + h0);
            int4 ic0 = __ldg(gi + 0), ic1 = __ldg(gi + 1);
            int4 ic2 = __ldg(gi + 2), ic3 = __ldg(gi + 3);

#pragma unroll
            for (int i = 0; i < 16; i++) accu[i] = 0;

            const uint8_t* vbase = g_v1B + h0;
            int j = 0;
            while (j < n) {
                int e = j + 16; if (e > n) e = n;     // chunk of <=16 rows
                unsigned pa = 0, pb = 0, pc = 0, pd = 0;
                for (; j < e; j++) {
                    uint4 R = *(const uint4*)(vbase + ((size_t)lb[j] << 12));
                    pa += R.x; pb += R.y; pc += R.z; pd += R.w;
                }
                accu[0]  = __dp4a(pa, 0x00000001u, accu[0]);
                accu[1]  = __dp4a(pa, 0x00000100u, accu[1]);
                accu[2]  = __dp4a(pa, 0x00010000u, accu[2]);
                accu[3]  = __dp4a(pa, 0x01000000u, accu[3]);
                accu[4]  = __dp4a(pb, 0x00000001u, accu[4]);
                accu[5]  = __dp4a(pb, 0x00000100u, accu[5]);
                accu[6]  = __dp4a(pb, 0x00010000u, accu[6]);
                accu[7]  = __dp4a(pb, 0x01000000u, accu[7]);
                accu[8]  = __dp4a(pc, 0x00000001u, accu[8]);
                accu[9]  = __dp4a(pc, 0x00000100u, accu[9]);
                accu[10] = __dp4a(pc, 0x00010000u, accu[10]);
                accu[11] = __dp4a(pc, 0x01000000u, accu[11]);
                accu[12] = __dp4a(pd, 0x00000001u, accu[12]);
                accu[13] = __dp4a(pd, 0x00000100u, accu[13]);
                accu[14] = __dp4a(pd, 0x00010000u, accu[14]);
                accu[15] = __dp4a(pd, 0x01000000u, accu[15]);
            }
            const int bias = n * 8;

            // ---- LIF (reset by prev spike -> threshold -> decay/integrate) ----
            unsigned nm = 0;
            LIF1(0,  ic0.x); LIF1(1,  ic0.y); LIF1(2,  ic0.z); LIF1(3,  ic0.w);
            LIF1(4,  ic1.x); LIF1(5,  ic1.y); LIF1(6,  ic1.z); LIF1(7,  ic1.w);
            LIF1(8,  ic2.x); LIF1(9,  ic2.y); LIF1(10, ic2.z); LIF1(11, ic2.w);
            LIF1(12, ic3.x); LIF1(13, ic3.y); LIF1(14, ic3.z); LIF1(15, ic3.w);

            // ---- append new spikes ----
            int c = __popc(nm);
            if (c) {
                int pos = atomicAdd(&cnts[t + 1], c);
                unsigned b = nm;
                while (b) {
                    int i = __ffs(b) - 1;
                    b &= b - 1;
                    listbuf[pn][pos++] = h0 + i;
                }
            }
            spm = nm;
        } else if (t > 0) {
            // ---- readout for step t-1 (warp 8, overlapped with gather) ----
            int ro = 0;
            for (int j = 0; j < n; j++)
                ro += (int)g_w2T[(lb[j] << 5) + ro_lane];
            rm = rm - (rm >> 3) + rs;
            rs = rs - (rs >> 4) + ro;
            if (ro_lane < O) ((float*)out)[ro_lane * T + (t - 1)] = (float)rm;
        }

        __syncthreads();                 // publish listbuf[pn] + cnts[t+1]
    }

    // ---- epilogue: readout for t = T-1 (no gather needed) ----
    if (!gth) {
        rm = rm - (rm >> 3) + rs;
        if (ro_lane < O) ((float*)out)[ro_lane * T + (T - 1)] = (float)rm;
    }
}

// ---------------- launcher ----------------
extern "C" void kernel_launch(void* const* d_in, const int* in_sizes, int n_in,
                              void* d_out, int out_size) {
    // Identify inputs by element count (order-independent; all sizes unique).
    const void *spk = 0, *w1 = 0, *v1 = 0, *w2 = 0;
    for (int i = 0; i < n_in; i++) {
        switch (in_sizes[i]) {
            case T * NI:  spk = d_in[i]; break;   // 700,000
            case H * NI:  w1  = d_in[i]; break;   // 2,867,200
            case H * H:   v1  = d_in[i]; break;   // 16,777,216
            case O * H:   w2  = d_in[i]; break;   // 81,920
        }
    }

    detect_dtype_kernel<<<1, 1>>>(w1);

    pack_w1_kernel<<<(H * NIP + 255) / 256, 256>>>(w1);
    pack_sp_kernel<<<(TPAD * NIP + 255) / 256, 256>>>(spk);
    pack_w2_kernel<<<(H * 32 + 255) / 256, 256>>>(w2);
    dim3 gtr(H / 64, H / 64);
    pack_v1T_kernel<<<gtr, 256>>>(v1);

    dim3 gg(TPAD / 32, H / 256);          // 32 x 16 blocks, 256 threads
    gemm_in_imma<<<gg, 256>>>();

    snn_recur_kernel<<<1, 288>>>(d_out);
}